// round 7
// baseline (speedup 1.0000x reference)
#include <cuda_runtime.h>
#include <cuda_bf16.h>
#include <cstdint>

// Volume rendering composite.
// Inputs: depth [N,192,1] f32, rgb [N,192,3] f32, sigma [N,192,1] f32
// Output (concat, f32): color [N,3], depth_out [N,1], acc_map [N,1], weights [N,192,1]
//
// One warp per ray. Lane l owns sample PAIRS {64k+2l, 64k+2l+1}, k=0..2, so
// every global load/store is a warp-contiguous 256B LDG.64/STG.64 (minimal
// L1tex wavefronts). Transmittance via 3 chained warp scans (pair product ->
// 5-step shuffle scan -> carry). Weights exchanged through smem so the rgb
// pass (also fully coalesced) can pick up the right w per float.

#define NRAYS 65536
#define NSAMP 192
#define WARPS_PER_BLK 8

__device__ __forceinline__ float ex2_approx(float x) {
    float r; asm("ex2.approx.f32 %0, %1;" : "=f"(r) : "f"(x)); return r;
}
__device__ __forceinline__ float tanh_approx(float x) {
    float r; asm("tanh.approx.f32 %0, %1;" : "=f"(r) : "f"(x)); return r;
}
// sigmoid(x) = 0.5*tanh(x/2) + 0.5  (one MUFU op)
__device__ __forceinline__ float sigmoid_fast(float x) {
    return fmaf(0.5f, tanh_approx(0.5f * x), 0.5f);
}

__global__ void __launch_bounds__(256, 6)
volrend_kernel(const float* __restrict__ depth,
               const float* __restrict__ rgb,
               const float* __restrict__ sigma,
               float* __restrict__ out)
{
    const int wid  = threadIdx.x >> 5;
    const int lane = threadIdx.x & 31;
    const int ray  = blockIdx.x * WARPS_PER_BLK + wid;

    __shared__ float w_sh[WARPS_PER_BLK][NSAMP];

    const float BOARDER = 1e10f;
    const float EPS     = 1e-10f;
    const float LOG2E   = 1.4426950408889634f;
    const unsigned FULL = 0xffffffffu;

    const float2* __restrict__ D2 = (const float2*)(depth + (size_t)ray * NSAMP);
    const float2* __restrict__ G2 = (const float2*)(sigma + (size_t)ray * NSAMP);

    // ---- front-batched, perfectly coalesced loads (256B per LDG.64) ----
    float2 dp[3], gp[3];
    #pragma unroll
    for (int k = 0; k < 3; ++k) {
        dp[k] = __ldcs(D2 + 32 * k + lane);
        gp[k] = __ldcs(G2 + 32 * k + lane);
    }

    // next-sample depth for the 2nd element of each pair
    float nd[3];
    #pragma unroll
    for (int k = 0; k < 3; ++k)
        nd[k] = __shfl_down_sync(FULL, dp[k].x, 1);     // lanes 0..30
    // chunk boundaries: lane31 of chunk k continues at lane0 of chunk k+1
    const float b1 = __shfl_sync(FULL, dp[1].x, 0);
    const float b2 = __shfl_sync(FULL, dp[2].x, 0);
    if (lane == 31) {
        nd[0] = b1;
        nd[1] = b2;
        nd[2] = BOARDER + dp[2].y;   // makes delta = BOARDER
    }

    // ---- 3 chained scans: survival products -> transmittance -> weights ----
    float w0[3], w1[3];
    float carry = 1.0f, dacc = 0.0f, aacc = 0.0f;
    #pragma unroll
    for (int k = 0; k < 3; ++k) {
        const float del0 = dp[k].y - dp[k].x;
        const float del1 = nd[k]   - dp[k].y;
        const float e0 = ex2_approx(-(fmaxf(gp[k].x, 0.0f) * del0) * LOG2E);
        const float e1 = ex2_approx(-(fmaxf(gp[k].y, 0.0f) * del1) * LOG2E);
        const float s0 = e0 + EPS;
        const float s1 = e1 + EPS;

        // warp scan over per-lane pair products
        float incl = s0 * s1;
        #pragma unroll
        for (int off = 1; off < 32; off <<= 1) {
            const float v = __shfl_up_sync(FULL, incl, off);
            if (lane >= off) incl *= v;
        }
        float excl = __shfl_up_sync(FULL, incl, 1);
        if (lane == 0) excl = 1.0f;

        const float T0 = carry * excl;
        w0[k] = (1.0f - e0) * T0;
        w1[k] = (1.0f - e1) * (T0 * s0);
        carry *= __shfl_sync(FULL, incl, 31);

        dacc = fmaf(w0[k], dp[k].x, fmaf(w1[k], dp[k].y, dacc));
        aacc += w0[k] + w1[k];
    }

    // ---- store weights: coalesced gmem + smem for the rgb exchange ----
    float2* __restrict__ W2 =
        (float2*)(out + (size_t)NRAYS * 5 + (size_t)ray * NSAMP);
    #pragma unroll
    for (int k = 0; k < 3; ++k) {
        __stcs(W2 + 32 * k + lane, make_float2(w0[k], w1[k]));
        w_sh[wid][64 * k + 2 * lane]     = w0[k];
        w_sh[wid][64 * k + 2 * lane + 1] = w1[k];
    }
    __syncwarp();

    // ---- rgb pass: coalesced float2 loads; map float index -> (sample, ch) ----
    const float2* __restrict__ R2 = (const float2*)(rgb + (size_t)ray * NSAMP * 3);
    float c0 = 0.f, c1 = 0.f, c2 = 0.f;
    #pragma unroll
    for (int j = 0; j < 9; ++j) {
        const float2 r = __ldcs(R2 + 32 * j + lane);
        const int f0 = 64 * j + 2 * lane;
        const int f1 = f0 + 1;
        const int sA = f0 / 3, chA = f0 - 3 * sA;
        const int sB = f1 / 3, chB = f1 - 3 * sB;
        const float vA = sigmoid_fast(r.x) * w_sh[wid][sA];
        const float vB = sigmoid_fast(r.y) * w_sh[wid][sB];
        c0 += (chA == 0) ? vA : 0.0f;
        c1 += (chA == 1) ? vA : 0.0f;
        c2 += (chA == 2) ? vA : 0.0f;
        c0 += (chB == 0) ? vB : 0.0f;
        c1 += (chB == 1) ? vB : 0.0f;
        c2 += (chB == 2) ? vB : 0.0f;
    }

    // ---- warp reduction ----
    #pragma unroll
    for (int off = 16; off > 0; off >>= 1) {
        c0   += __shfl_down_sync(FULL, c0,   off);
        c1   += __shfl_down_sync(FULL, c1,   off);
        c2   += __shfl_down_sync(FULL, c2,   off);
        dacc += __shfl_down_sync(FULL, dacc, off);
        aacc += __shfl_down_sync(FULL, aacc, off);
    }
    if (lane == 0) {
        out[3 * ray + 0] = c0;
        out[3 * ray + 1] = c1;
        out[3 * ray + 2] = c2;
        out[(size_t)NRAYS * 3 + ray] = dacc;
        out[(size_t)NRAYS * 4 + ray] = aacc;
    }
}

extern "C" void kernel_launch(void* const* d_in, const int* in_sizes, int n_in,
                              void* d_out, int out_size)
{
    const float* depth = (const float*)d_in[0];
    const float* rgb   = (const float*)d_in[1];
    const float* sigma = (const float*)d_in[2];
    float* out = (float*)d_out;

    const int threads = 32 * WARPS_PER_BLK;     // 256
    const int blocks  = NRAYS / WARPS_PER_BLK;  // 8192
    volrend_kernel<<<blocks, threads>>>(depth, rgb, sigma, out);
}

// round 8
// speedup vs baseline: 1.1382x; 1.1382x over previous
#include <cuda_runtime.h>
#include <cuda_bf16.h>
#include <cstdint>

// Volume rendering composite.
// Inputs: depth [N,192,1] f32, rgb [N,192,3] f32, sigma [N,192,1] f32
// Output (concat, f32): color [N,3], depth_out [N,1], acc_map [N,1], weights [N,192,1]
//
// One warp per ray.
//  - ALL global loads/stores are warp-contiguous 256B LDG.64/STG.64
//    (minimum L1tex wavefronts), staged through per-warp shared memory.
//  - Compute ownership is lane -> samples [6l, 6l+6): single 5-step warp scan,
//    compile-time rgb channel mapping (no div/mod, no predicated selects).
//  - Weights transposed back through smem for the coalesced global store.

#define NRAYS 65536
#define NSAMP 192
#define WPB   8

__device__ __forceinline__ float ex2_approx(float x) {
    float r; asm("ex2.approx.f32 %0, %1;" : "=f"(r) : "f"(x)); return r;
}
__device__ __forceinline__ float tanh_approx(float x) {
    float r; asm("tanh.approx.f32 %0, %1;" : "=f"(r) : "f"(x)); return r;
}
// sigmoid(x) = 0.5*tanh(x/2) + 0.5  (one MUFU op)
__device__ __forceinline__ float sigmoid_fast(float x) {
    return fmaf(0.5f, tanh_approx(0.5f * x), 0.5f);
}

__global__ void __launch_bounds__(256, 6)
volrend_kernel(const float* __restrict__ depth,
               const float* __restrict__ rgb,
               const float* __restrict__ sigma,
               float* __restrict__ out)
{
    const int wid  = threadIdx.x >> 5;
    const int lane = threadIdx.x & 31;
    const int ray  = blockIdx.x * WPB + wid;

    // per-warp staging: depth [0,192), sigma [192,384) ; rgb 576 floats
    __shared__ __align__(16) float sds [WPB][NSAMP * 2 + 8];
    __shared__ __align__(16) float srgb[WPB][NSAMP * 3];

    const float BOARDER = 1e10f;
    const float EPS     = 1e-10f;
    const float LOG2E   = 1.4426950408889634f;
    const unsigned FULL = 0xffffffffu;

    const float2* __restrict__ D2 = (const float2*)(depth + (size_t)ray * NSAMP);
    const float2* __restrict__ G2 = (const float2*)(sigma + (size_t)ray * NSAMP);
    const float2* __restrict__ R2 = (const float2*)(rgb   + (size_t)ray * NSAMP * 3);

    // ---- coalesced global loads (front-batched, 15x LDG.64) ----
    float2 dv[3], gv[3];
    #pragma unroll
    for (int k = 0; k < 3; ++k) {
        dv[k] = __ldcs(D2 + 32 * k + lane);
        gv[k] = __ldcs(G2 + 32 * k + lane);
    }
    float2 rv[9];
    #pragma unroll
    for (int j = 0; j < 9; ++j) rv[j] = __ldcs(R2 + 32 * j + lane);

    // ---- stage to smem ----
    #pragma unroll
    for (int k = 0; k < 3; ++k) {
        *(float2*)&sds[wid][64 * k + 2 * lane]         = dv[k];
        *(float2*)&sds[wid][NSAMP + 64 * k + 2 * lane] = gv[k];
    }
    #pragma unroll
    for (int j = 0; j < 9; ++j)
        *(float2*)&srgb[wid][64 * j + 2 * lane] = rv[j];
    __syncwarp();

    // ---- lane reads its 6 consecutive samples [6l, 6l+6) ----
    float d[6], g[6];
    #pragma unroll
    for (int t = 0; t < 3; ++t) {
        const float2 a = *(const float2*)&sds[wid][6 * lane + 2 * t];
        const float2 b = *(const float2*)&sds[wid][NSAMP + 6 * lane + 2 * t];
        d[2 * t] = a.x; d[2 * t + 1] = a.y;
        g[2 * t] = b.x; g[2 * t + 1] = b.y;
    }
    const float dnext = (lane < 31) ? sds[wid][6 * lane + 6] : 0.0f;

    // ---- survival probs ----
    float surv[6];
    #pragma unroll
    for (int j = 0; j < 6; ++j) {
        const float dl = (j < 5) ? (d[j + 1] - d[j])
                                 : ((lane == 31) ? BOARDER : (dnext - d[5]));
        surv[j] = ex2_approx(-(fmaxf(g[j], 0.0f) * dl) * LOG2E) + EPS;
    }

    // ---- local exclusive prefix + single 5-step warp scan ----
    float Q[6];
    Q[0] = 1.0f;
    #pragma unroll
    for (int j = 1; j < 6; ++j) Q[j] = Q[j - 1] * surv[j - 1];
    float incl = Q[5] * surv[5];
    #pragma unroll
    for (int off = 1; off < 32; off <<= 1) {
        const float v = __shfl_up_sync(FULL, incl, off);
        if (lane >= off) incl *= v;
    }
    float excl = __shfl_up_sync(FULL, incl, 1);
    if (lane == 0) excl = 1.0f;

    // ---- weights + depth/acc accumulation ----
    float w[6];
    float dacc = 0.f, aacc = 0.f;
    #pragma unroll
    for (int j = 0; j < 6; ++j) {
        w[j]  = (1.0f - surv[j] + EPS) * (excl * Q[j]);
        dacc  = fmaf(w[j], d[j], dacc);
        aacc += w[j];
    }

    // ---- transpose weights through smem -> coalesced STG.64 ----
    __syncwarp();   // all lanes done reading depth region (incl. dnext)
    #pragma unroll
    for (int t = 0; t < 3; ++t)
        *(float2*)&sds[wid][6 * lane + 2 * t] = make_float2(w[2 * t], w[2 * t + 1]);
    __syncwarp();
    float2* __restrict__ W2 =
        (float2*)(out + (size_t)NRAYS * 5 + (size_t)ray * NSAMP);
    #pragma unroll
    for (int k = 0; k < 3; ++k)
        __stcs(W2 + 32 * k + lane, *(const float2*)&sds[wid][64 * k + 2 * lane]);

    // ---- rgb: lane reads its own 18 floats; (sample, channel) compile-time ----
    float c0 = 0.f, c1 = 0.f, c2 = 0.f;
    #pragma unroll
    for (int t = 0; t < 9; ++t) {
        const float2 r = *(const float2*)&srgb[wid][18 * lane + 2 * t];
        const int i0 = 2 * t, i1 = 2 * t + 1;           // constants after unroll
        const float v0 = sigmoid_fast(r.x) * w[i0 / 3];
        const float v1 = sigmoid_fast(r.y) * w[i1 / 3];
        if      (i0 % 3 == 0) c0 += v0;
        else if (i0 % 3 == 1) c1 += v0;
        else                  c2 += v0;
        if      (i1 % 3 == 0) c0 += v1;
        else if (i1 % 3 == 1) c1 += v1;
        else                  c2 += v1;
    }

    // ---- warp reduction ----
    #pragma unroll
    for (int off = 16; off > 0; off >>= 1) {
        c0   += __shfl_down_sync(FULL, c0,   off);
        c1   += __shfl_down_sync(FULL, c1,   off);
        c2   += __shfl_down_sync(FULL, c2,   off);
        dacc += __shfl_down_sync(FULL, dacc, off);
        aacc += __shfl_down_sync(FULL, aacc, off);
    }
    if (lane == 0) {
        out[3 * ray + 0] = c0;
        out[3 * ray + 1] = c1;
        out[3 * ray + 2] = c2;
        out[(size_t)NRAYS * 3 + ray] = dacc;
        out[(size_t)NRAYS * 4 + ray] = aacc;
    }
}

extern "C" void kernel_launch(void* const* d_in, const int* in_sizes, int n_in,
                              void* d_out, int out_size)
{
    const float* depth = (const float*)d_in[0];
    const float* rgb   = (const float*)d_in[1];
    const float* sigma = (const float*)d_in[2];
    float* out = (float*)d_out;

    const int threads = 32 * WPB;               // 256
    const int blocks  = NRAYS / WPB;            // 8192
    volrend_kernel<<<blocks, threads>>>(depth, rgb, sigma, out);
}

// round 9
// speedup vs baseline: 1.1564x; 1.0160x over previous
#include <cuda_runtime.h>
#include <cuda_bf16.h>
#include <cstdint>

// Volume rendering composite.
// Inputs: depth [N,192,1] f32, rgb [N,192,3] f32, sigma [N,192,1] f32
// Output (concat, f32): color [N,3], depth_out [N,1], acc_map [N,1], weights [N,192,1]
//
// One warp per ray.
//  - depth/sigma/weights: pair ownership (lane l owns samples {64k+2l, 64k+2l+1}),
//    every LDG/STG warp-contiguous 256B; 3 chained warp scans; weights stored
//    directly (no transpose).
//  - rgb: coalesced full-warp LDG.64; (sample,channel) via branch-free index
//    algebra (q = 2l/3, base = 2l%3, compile-time per-j corrections); channel
//    accumulation into base-rotated registers -> compile-time targets.
//  - smem: only a 192-float/warp weight-exchange buffer (6KB/block).

#define NRAYS 65536
#define NSAMP 192
#define WPB   8

__device__ __forceinline__ float ex2_approx(float x) {
    float r; asm("ex2.approx.f32 %0, %1;" : "=f"(r) : "f"(x)); return r;
}
__device__ __forceinline__ float tanh_approx(float x) {
    float r; asm("tanh.approx.f32 %0, %1;" : "=f"(r) : "f"(x)); return r;
}
// sigmoid(x) = 0.5*tanh(x/2) + 0.5  (one MUFU op)
__device__ __forceinline__ float sigmoid_fast(float x) {
    return fmaf(0.5f, tanh_approx(0.5f * x), 0.5f);
}

__global__ void __launch_bounds__(256, 7)
volrend_kernel(const float* __restrict__ depth,
               const float* __restrict__ rgb,
               const float* __restrict__ sigma,
               float* __restrict__ out)
{
    const int wid  = threadIdx.x >> 5;
    const int lane = threadIdx.x & 31;
    const int ray  = blockIdx.x * WPB + wid;

    __shared__ float w_sh[WPB][NSAMP];   // weight exchange only (6KB/block)

    const float BOARDER = 1e10f;
    const float EPS     = 1e-10f;
    const float LOG2E   = 1.4426950408889634f;
    const unsigned FULL = 0xffffffffu;

    const float2* __restrict__ D2 = (const float2*)(depth + (size_t)ray * NSAMP);
    const float2* __restrict__ G2 = (const float2*)(sigma + (size_t)ray * NSAMP);

    // ---- coalesced pair loads (256B per LDG.64) ----
    float2 dp[3], gp[3];
    #pragma unroll
    for (int k = 0; k < 3; ++k) {
        dp[k] = __ldcs(D2 + 32 * k + lane);
        gp[k] = __ldcs(G2 + 32 * k + lane);
    }

    // next-sample depth for the 2nd element of each pair
    float nd[3];
    #pragma unroll
    for (int k = 0; k < 3; ++k)
        nd[k] = __shfl_down_sync(FULL, dp[k].x, 1);      // lanes 0..30
    const float b1 = __shfl_sync(FULL, dp[1].x, 0);
    const float b2 = __shfl_sync(FULL, dp[2].x, 0);
    if (lane == 31) {
        nd[0] = b1;
        nd[1] = b2;
        nd[2] = BOARDER + dp[2].y;   // makes delta = BOARDER
    }

    // ---- 3 chained scans: survival -> transmittance -> weights ----
    float w0[3], w1[3];
    float carry = 1.0f, dacc = 0.0f, aacc = 0.0f;
    #pragma unroll
    for (int k = 0; k < 3; ++k) {
        const float del0 = dp[k].y - dp[k].x;
        const float del1 = nd[k]   - dp[k].y;
        const float e0 = ex2_approx(-(fmaxf(gp[k].x, 0.0f) * del0) * LOG2E);
        const float e1 = ex2_approx(-(fmaxf(gp[k].y, 0.0f) * del1) * LOG2E);
        const float s0 = e0 + EPS;
        const float s1 = e1 + EPS;

        float incl = s0 * s1;
        #pragma unroll
        for (int off = 1; off < 32; off <<= 1) {
            const float v = __shfl_up_sync(FULL, incl, off);
            if (lane >= off) incl *= v;
        }
        float excl = __shfl_up_sync(FULL, incl, 1);
        if (lane == 0) excl = 1.0f;

        const float T0 = carry * excl;
        w0[k] = (1.0f - e0) * T0;
        w1[k] = (1.0f - e1) * (T0 * s0);
        carry *= __shfl_sync(FULL, incl, 31);

        dacc = fmaf(w0[k], dp[k].x, fmaf(w1[k], dp[k].y, dacc));
        aacc += w0[k] + w1[k];
    }

    // ---- weights: direct coalesced STG.64 + smem exchange ----
    float2* __restrict__ W2 =
        (float2*)(out + (size_t)NRAYS * 5 + (size_t)ray * NSAMP);
    #pragma unroll
    for (int k = 0; k < 3; ++k) {
        const float2 wv = make_float2(w0[k], w1[k]);
        __stcs(W2 + 32 * k + lane, wv);
        *(float2*)&w_sh[wid][64 * k + 2 * lane] = wv;
    }
    __syncwarp();

    // ---- rgb pass: coalesced loads + branch-free index algebra ----
    // lane's first float of chunk j is f0 = 64j + 2l = 3*sA + chA with
    //   q = 2l/3, base = 2l%3, sA = 21j + q + floor((j+base)/3),
    //   chA = (j+base)%3.  A[i] accumulates channel (base+i)%3, so vA -> A[j%3].
    const float2* __restrict__ R2 = (const float2*)(rgb + (size_t)ray * NSAMP * 3);
    const int u    = 2 * lane;
    const int q    = u / 3;
    const int base = u - 3 * q;
    const int e0f  = (base == 0);
    const int e1f  = (base == 1);
    const int e2f  = (base == 2);
    const float* __restrict__ wrow = w_sh[wid];

    float A0 = 0.f, A1 = 0.f, A2 = 0.f;
    #pragma unroll
    for (int j = 0; j < 9; ++j) {
        const float2 r = __ldcs(R2 + 32 * j + lane);
        const int jm = j % 3;                 // compile-time
        // floor((j+base)/3) = j/3 + corr,  corr selected per jm
        const int corr = (jm == 0) ? 0 : (jm == 1) ? e2f : (e1f + e2f);
        const int sA   = 21 * j + (j / 3) + q + corr;
        // chA==2  <=>  base == (2-jm)%3
        const int sB   = sA + ((jm == 0) ? e2f : (jm == 1) ? e1f : e0f);

        const float vA = sigmoid_fast(r.x) * wrow[sA];
        const float vB = sigmoid_fast(r.y) * wrow[sB];
        // vA -> A[j%3], vB -> A[(j+1)%3]   (compile-time targets)
        if      (jm == 0) { A0 += vA; A1 += vB; }
        else if (jm == 1) { A1 += vA; A2 += vB; }
        else              { A2 += vA; A0 += vB; }
    }

    // A[i] holds channel (base+i)%3 -> rotate into c0,c1,c2
    float c0, c1, c2;
    if      (base == 0) { c0 = A0; c1 = A1; c2 = A2; }
    else if (base == 1) { c0 = A2; c1 = A0; c2 = A1; }
    else                { c0 = A1; c1 = A2; c2 = A0; }

    // ---- warp reduction ----
    #pragma unroll
    for (int off = 16; off > 0; off >>= 1) {
        c0   += __shfl_down_sync(FULL, c0,   off);
        c1   += __shfl_down_sync(FULL, c1,   off);
        c2   += __shfl_down_sync(FULL, c2,   off);
        dacc += __shfl_down_sync(FULL, dacc, off);
        aacc += __shfl_down_sync(FULL, aacc, off);
    }
    if (lane == 0) {
        out[3 * ray + 0] = c0;
        out[3 * ray + 1] = c1;
        out[3 * ray + 2] = c2;
        out[(size_t)NRAYS * 3 + ray] = dacc;
        out[(size_t)NRAYS * 4 + ray] = aacc;
    }
}

extern "C" void kernel_launch(void* const* d_in, const int* in_sizes, int n_in,
                              void* d_out, int out_size)
{
    const float* depth = (const float*)d_in[0];
    const float* rgb   = (const float*)d_in[1];
    const float* sigma = (const float*)d_in[2];
    float* out = (float*)d_out;

    const int threads = 32 * WPB;               // 256
    const int blocks  = NRAYS / WPB;            // 8192
    volrend_kernel<<<blocks, threads>>>(depth, rgb, sigma, out);
}

// round 10
// speedup vs baseline: 1.1626x; 1.0054x over previous
#include <cuda_runtime.h>
#include <cuda_bf16.h>
#include <cstdint>

// Volume rendering composite.
// Inputs: depth [N,192,1] f32, rgb [N,192,3] f32, sigma [N,192,1] f32
// Output (concat, f32): color [N,3], depth_out [N,1], acc_map [N,1], weights [N,192,1]
//
// One warp per ray, 128-bit memory ops throughout:
//  - depth/sigma: LDG.128 (lane owns samples 4l..4l+3) + LDG.64 (128+2l..+1)
//  - weights: STG.128 + STG.64 (direct, coalesced) + smem exchange
//  - rgb: 4x LDG.128 + 1x LDG.64, branch-free compile-time channel algebra
//  - transmittance: 2 chained warp scans (product-of-4 then product-of-2)

#define NRAYS 65536
#define NSAMP 192
#define WPB   8

__device__ __forceinline__ float ex2_approx(float x) {
    float r; asm("ex2.approx.f32 %0, %1;" : "=f"(r) : "f"(x)); return r;
}
__device__ __forceinline__ float tanh_approx(float x) {
    float r; asm("tanh.approx.f32 %0, %1;" : "=f"(r) : "f"(x)); return r;
}
// sigmoid(x) = 0.5*tanh(x/2) + 0.5  (one MUFU op)
__device__ __forceinline__ float sigmoid_fast(float x) {
    return fmaf(0.5f, tanh_approx(0.5f * x), 0.5f);
}

__global__ void __launch_bounds__(256, 7)
volrend_kernel(const float* __restrict__ depth,
               const float* __restrict__ rgb,
               const float* __restrict__ sigma,
               float* __restrict__ out)
{
    const int wid  = threadIdx.x >> 5;
    const int lane = threadIdx.x & 31;
    const int ray  = blockIdx.x * WPB + wid;

    __shared__ __align__(16) float w_sh[WPB][NSAMP];   // weight exchange (6KB)

    const float BOARDER = 1e10f;
    const float EPS     = 1e-10f;
    const float LOG2E   = 1.4426950408889634f;
    const unsigned FULL = 0xffffffffu;

    const float* dbase = depth + (size_t)ray * NSAMP;
    const float* gbase = sigma + (size_t)ray * NSAMP;

    // ---- coalesced loads: LDG.128 (samples 0..127) + LDG.64 (128..191) ----
    const float4 dA = __ldcs((const float4*)dbase + lane);          // 4l..4l+3
    const float2 dB = __ldcs((const float2*)(dbase + 128) + lane);  // 128+2l..+1
    const float4 gA = __ldcs((const float4*)gbase + lane);
    const float2 gB = __ldcs((const float2*)(gbase + 128) + lane);

    // next-sample depths across lane boundaries
    float ndA = __shfl_down_sync(FULL, dA.x, 1);       // d[4l+4], lanes 0..30
    const float bA = __shfl_sync(FULL, dB.x, 0);       // d[128]
    if (lane == 31) ndA = bA;
    const float ndB = __shfl_down_sync(FULL, dB.x, 1); // d[128+2l+2]

    // ---- chunk A: 4 survivals, product scan ----
    const float eA0 = ex2_approx(-(fmaxf(gA.x, 0.f) * (dA.y - dA.x)) * LOG2E);
    const float eA1 = ex2_approx(-(fmaxf(gA.y, 0.f) * (dA.z - dA.y)) * LOG2E);
    const float eA2 = ex2_approx(-(fmaxf(gA.z, 0.f) * (dA.w - dA.z)) * LOG2E);
    const float eA3 = ex2_approx(-(fmaxf(gA.w, 0.f) * (ndA  - dA.w)) * LOG2E);
    const float sA0 = eA0 + EPS, sA1 = eA1 + EPS, sA2 = eA2 + EPS, sA3 = eA3 + EPS;

    float inclA = (sA0 * sA1) * (sA2 * sA3);
    #pragma unroll
    for (int off = 1; off < 32; off <<= 1) {
        const float v = __shfl_up_sync(FULL, inclA, off);
        if (lane >= off) inclA *= v;
    }
    float exclA = __shfl_up_sync(FULL, inclA, 1);
    if (lane == 0) exclA = 1.0f;

    float T = exclA;
    const float w0 = (1.0f - eA0) * T;  T *= sA0;
    const float w1 = (1.0f - eA1) * T;  T *= sA1;
    const float w2 = (1.0f - eA2) * T;  T *= sA2;
    const float w3 = (1.0f - eA3) * T;
    const float carry = __shfl_sync(FULL, inclA, 31);

    float dacc = fmaf(w0, dA.x, fmaf(w1, dA.y, fmaf(w2, dA.z, w3 * dA.w)));
    float aacc = (w0 + w1) + (w2 + w3);

    // ---- chunk B: 2 survivals, product scan seeded by carry ----
    const float eB0 = ex2_approx(-(fmaxf(gB.x, 0.f) * (dB.y - dB.x)) * LOG2E);
    const float delB1 = (lane == 31) ? BOARDER : (ndB - dB.y);
    const float eB1 = ex2_approx(-(fmaxf(gB.y, 0.f) * delB1) * LOG2E);
    const float sB0 = eB0 + EPS, sB1 = eB1 + EPS;

    float inclB = sB0 * sB1;
    #pragma unroll
    for (int off = 1; off < 32; off <<= 1) {
        const float v = __shfl_up_sync(FULL, inclB, off);
        if (lane >= off) inclB *= v;
    }
    float exclB = __shfl_up_sync(FULL, inclB, 1);
    if (lane == 0) exclB = 1.0f;

    const float TB  = carry * exclB;
    const float wB0 = (1.0f - eB0) * TB;
    const float wB1 = (1.0f - eB1) * (TB * sB0);

    dacc = fmaf(wB0, dB.x, fmaf(wB1, dB.y, dacc));
    aacc += wB0 + wB1;

    // ---- weights: STG.128 + STG.64 + smem exchange ----
    float* __restrict__ wbase = out + (size_t)NRAYS * 5 + (size_t)ray * NSAMP;
    const float4 wa = make_float4(w0, w1, w2, w3);
    const float2 wb = make_float2(wB0, wB1);
    __stcs((float4*)wbase + lane, wa);
    __stcs((float2*)(wbase + 128) + lane, wb);
    *(float4*)&w_sh[wid][4 * lane]       = wa;
    *(float2*)&w_sh[wid][128 + 2 * lane] = wb;
    __syncwarp();

    // ---- rgb: 4x LDG.128 + 1x LDG.64, compile-time channel algebra ----
    // float i of chunk j at lane l: global float f = 128j + 4l + i
    //   sample = 42j + l + a + g(j,b) + off(i),  a = l/3, b = l%3
    //   channel = (2j + l + i) mod 3 -> accumulate into B[(2j+i) mod 3]
    const float* __restrict__ rbase = rgb + (size_t)ray * NSAMP * 3;
    const float* __restrict__ wrow  = w_sh[wid];
    const int a = lane / 3;
    const int b = lane - 3 * a;
    const int bge1 = (b >= 1), beq2 = (b == 2);
    const int beq0 = (b == 0), bne1 = (b != 1);
    const int beq1 = (b == 1), bne2 = (b != 2);

    float B0 = 0.f, B1 = 0.f, B2 = 0.f;
    #pragma unroll
    for (int j = 0; j < 4; ++j) {
        const float4 r = __ldcs((const float4*)rbase + 32 * j + lane);
        // per-j (compile-time) selections of the runtime booleans
        int g, p1, p2;
        if      (j == 0) { g = 0;        p2 = beq2; p1 = bge1; }
        else if (j == 1) { g = bge1;     p2 = beq0; p1 = bne1; }
        else if (j == 2) { g = 1 + beq2; p2 = beq1; p1 = bne2; }
        else             { g = 2;        p2 = beq2; p1 = bge1; }
        const int s0 = 42 * j + lane + a + g;

        const float v0 = sigmoid_fast(r.x) * wrow[s0];
        const float v1 = sigmoid_fast(r.y) * wrow[s0 + p2];
        const float v2 = sigmoid_fast(r.z) * wrow[s0 + p1];
        const float v3 = sigmoid_fast(r.w) * wrow[s0 + 1];

        // m(i) = (2j + i) % 3 (compile-time targets)
        if      (j == 0) { B0 += v0; B1 += v1; B2 += v2; B0 += v3; }
        else if (j == 1) { B2 += v0; B0 += v1; B1 += v2; B2 += v3; }
        else if (j == 2) { B1 += v0; B2 += v1; B0 += v2; B1 += v3; }
        else             { B0 += v0; B1 += v1; B2 += v2; B0 += v3; }
    }

    // rotate B into real channels: channel k = B[(k - l) mod 3]
    float c0, c1, c2;
    if      (b == 0) { c0 = B0; c1 = B1; c2 = B2; }
    else if (b == 1) { c0 = B2; c1 = B0; c2 = B1; }
    else             { c0 = B1; c1 = B2; c2 = B0; }

    // tail chunk: floats 512 + 2l, 513 + 2l (LDG.64)
    {
        const float2 r = __ldcs((const float2*)(rbase + 512) + lane);
        const int f0  = 512 + 2 * lane;
        const int s0  = f0 / 3;             // computed once (magic-mul)
        const int ch0 = f0 - 3 * s0;
        const float v0 = sigmoid_fast(r.x) * wrow[s0];
        const float v1 = sigmoid_fast(r.y) * wrow[s0 + (ch0 == 2)];
        const int ch1 = (ch0 + 1 == 3) ? 0 : ch0 + 1;
        c0 += (ch0 == 0) ? v0 : 0.f;
        c1 += (ch0 == 1) ? v0 : 0.f;
        c2 += (ch0 == 2) ? v0 : 0.f;
        c0 += (ch1 == 0) ? v1 : 0.f;
        c1 += (ch1 == 1) ? v1 : 0.f;
        c2 += (ch1 == 2) ? v1 : 0.f;
    }

    // ---- warp reduction ----
    #pragma unroll
    for (int off = 16; off > 0; off >>= 1) {
        c0   += __shfl_down_sync(FULL, c0,   off);
        c1   += __shfl_down_sync(FULL, c1,   off);
        c2   += __shfl_down_sync(FULL, c2,   off);
        dacc += __shfl_down_sync(FULL, dacc, off);
        aacc += __shfl_down_sync(FULL, aacc, off);
    }
    if (lane == 0) {
        out[3 * ray + 0] = c0;
        out[3 * ray + 1] = c1;
        out[3 * ray + 2] = c2;
        out[(size_t)NRAYS * 3 + ray] = dacc;
        out[(size_t)NRAYS * 4 + ray] = aacc;
    }
}

extern "C" void kernel_launch(void* const* d_in, const int* in_sizes, int n_in,
                              void* d_out, int out_size)
{
    const float* depth = (const float*)d_in[0];
    const float* rgb   = (const float*)d_in[1];
    const float* sigma = (const float*)d_in[2];
    float* out = (float*)d_out;

    const int threads = 32 * WPB;               // 256
    const int blocks  = NRAYS / WPB;            // 8192
    volrend_kernel<<<blocks, threads>>>(depth, rgb, sigma, out);
}